// round 8
// baseline (speedup 1.0000x reference)
#include <cuda_runtime.h>
#include <cuda_bf16.h>

#define N_NODES 50000
#define N_EDGES 600000
#define N_GRAPHS 64

// ---------------- scratch (no allocations allowed) ----------------
__device__ float g_t[(size_t)N_NODES * 128];   // GEMM output u = dinv * (h@W)
__device__ float g_h[(size_t)N_NODES * 128];   // layer activations
__device__ float g_dinv[N_NODES];
__device__ int   g_indeg[N_NODES];
__device__ int   g_rowptr[N_NODES + 1];
__device__ int   g_cursor[N_NODES];
__device__ int   g_csrsrc[N_EDGES];
__device__ float g_pool[N_GRAPHS * 64];
__device__ float g_cnt[N_GRAPHS];
__device__ int   g_is64;                       // 1 if edge_index/batch are int64

// index loader robust to int32 vs int64 storage
__device__ __forceinline__ int load_idx(const void* __restrict__ p, size_t i) {
    if (g_is64) return (int)((const long long*)p)[i];
    return ((const int*)p)[i];
}

// ---------------- dtype detection ----------------
// If edge_index is int64 (little-endian), the high 32-bit word of every element
// is 0 (values < 50000). If int32, those words hold real random indices.
__global__ void k_detect(const int* __restrict__ ei_words) {
    int lane = threadIdx.x;
    int nz = 0;
    for (int i = lane; i < 256; i += 32)
        nz |= ei_words[2 * i + 1];              // candidate int64 high words
    for (int off = 16; off; off >>= 1)
        nz |= __shfl_xor_sync(0xffffffffu, nz, off);
    if (lane == 0) g_is64 = (nz == 0) ? 1 : 0;
}

// ---------------- prep kernels ----------------
__global__ void k_zero() {
    int i = blockIdx.x * blockDim.x + threadIdx.x;
    int stride = gridDim.x * blockDim.x;
    for (int j = i; j < N_NODES; j += stride) { g_indeg[j] = 0; g_cursor[j] = 0; }
    if (i < N_GRAPHS * 64) g_pool[i] = 0.f;
    if (i < N_GRAPHS) g_cnt[i] = 0.f;
}

__global__ void k_hist(const void* __restrict__ ei) {
    int e = blockIdx.x * blockDim.x + threadIdx.x;
    if (e < N_EDGES) {
        int c = load_idx(ei, (size_t)N_EDGES + e);
        atomicAdd(&g_indeg[c], 1);
    }
}

// single-block inclusive scan over indeg -> rowptr; also dinv = rsqrt(indeg+1)
__global__ void k_scan() {
    __shared__ int s[1024];
    __shared__ int carry;
    int tid = threadIdx.x;
    if (tid == 0) { carry = 0; g_rowptr[0] = 0; }
    __syncthreads();
    for (int base = 0; base < N_NODES; base += 1024) {
        int i = base + tid;
        int v = (i < N_NODES) ? g_indeg[i] : 0;
        if (i < N_NODES) g_dinv[i] = rsqrtf((float)(v + 1));
        s[tid] = v;
        __syncthreads();
        for (int off = 1; off < 1024; off <<= 1) {
            int t = (tid >= off) ? s[tid - off] : 0;
            __syncthreads();
            s[tid] += t;
            __syncthreads();
        }
        if (i < N_NODES) g_rowptr[i + 1] = carry + s[tid];
        __syncthreads();
        if (tid == 0) carry += s[1023];
        __syncthreads();
    }
}

__global__ void k_fill(const void* __restrict__ ei) {
    int e = blockIdx.x * blockDim.x + threadIdx.x;
    if (e < N_EDGES) {
        int c = load_idx(ei, (size_t)N_EDGES + e);
        int pos = g_rowptr[c] + atomicAdd(&g_cursor[c], 1);
        g_csrsrc[pos] = load_idx(ei, e);
    }
}

// ---------------- GEMM: g_t = dinv * (A @ W),  A:[N,128], W:[128,NC] ----------------
// Static smem only (<=48KB): A tile 64x128 resident, W staged in 32-row k-chunks.
template <int NC, bool FROM_GH>
__global__ __launch_bounds__(256) void k_gemm(const float* __restrict__ Ax,
                                              const float* __restrict__ W) {
    const float* __restrict__ A = FROM_GH ? (const float*)g_h : Ax;
    __shared__ float As[64 * 128];   // 32 KB
    __shared__ float Ws[32 * NC];    // 16 KB (NC=128) / 8 KB (NC=64)
    int tid = threadIdx.x;
    int base = blockIdx.x * 64;

    // stage A tile (float4, coalesced)
    #pragma unroll
    for (int i = tid; i < 64 * 128 / 4; i += 256) {
        int r = i >> 5, c4 = i & 31;
        float4 v;
        if (base + r < N_NODES) v = *(const float4*)(A + (size_t)(base + r) * 128 + c4 * 4);
        else v = make_float4(0.f, 0.f, 0.f, 0.f);
        ((float4*)As)[i] = v;
    }

    int tx = tid & 31, ty = tid >> 5;          // 8 warps, warp ty -> rows [8*ty, 8*ty+8)
    constexpr int CJ = NC / 32;                // cols per lane (stride-32, conflict-free)
    float acc[8][CJ];
    #pragma unroll
    for (int i = 0; i < 8; i++)
        #pragma unroll
        for (int j = 0; j < CJ; j++) acc[i][j] = 0.f;

    #pragma unroll
    for (int kc = 0; kc < 4; kc++) {           // 4 k-chunks of 32
        __syncthreads();
        #pragma unroll
        for (int i = tid; i < 32 * NC / 4; i += 256)
            ((float4*)Ws)[i] = ((const float4*)(W + kc * 32 * NC))[i];
        __syncthreads();

        #pragma unroll 4
        for (int k = 0; k < 32; k++) {
            float b[CJ];
            #pragma unroll
            for (int j = 0; j < CJ; j++) b[j] = Ws[k * NC + tx + 32 * j];
            #pragma unroll
            for (int i = 0; i < 8; i++) {
                float a = As[(ty * 8 + i) * 128 + kc * 32 + k];  // warp-broadcast LDS
                #pragma unroll
                for (int j = 0; j < CJ; j++) acc[i][j] = fmaf(a, b[j], acc[i][j]);
            }
        }
    }

    #pragma unroll
    for (int i = 0; i < 8; i++) {
        int r = base + ty * 8 + i;
        if (r < N_NODES) {
            float d = g_dinv[r];
            #pragma unroll
            for (int j = 0; j < CJ; j++)
                g_t[(size_t)r * NC + tx + 32 * j] = d * acc[i][j];
        }
    }
}

// ---------------- aggregation: g_h[v] = relu(dinv[v]*(u[v] + sum_in u[src]) + b) ----------------
template <int NC>
__global__ void k_agg(const float* __restrict__ bias) {
    int gw = (blockIdx.x * blockDim.x + threadIdx.x) >> 5;  // warp per node
    int lane = threadIdx.x & 31;
    if (gw >= N_NODES) return;
    int beg = g_rowptr[gw], end = g_rowptr[gw + 1];
    float d = g_dinv[gw];

    if constexpr (NC == 128) {
        float4 a = *((const float4*)(g_t + (size_t)gw * NC) + lane);  // self-loop term
        for (int e = beg; e < end; e++) {
            int s = g_csrsrc[e];                                      // broadcast load
            float4 u = *((const float4*)(g_t + (size_t)s * NC) + lane);
            a.x += u.x; a.y += u.y; a.z += u.z; a.w += u.w;
        }
        float4 bb = *((const float4*)bias + lane);
        float4 o;
        o.x = fmaxf(fmaf(d, a.x, bb.x), 0.f);
        o.y = fmaxf(fmaf(d, a.y, bb.y), 0.f);
        o.z = fmaxf(fmaf(d, a.z, bb.z), 0.f);
        o.w = fmaxf(fmaf(d, a.w, bb.w), 0.f);
        *((float4*)(g_h + (size_t)gw * NC) + lane) = o;
    } else {  // NC == 64
        float2 a = *((const float2*)(g_t + (size_t)gw * NC) + lane);
        for (int e = beg; e < end; e++) {
            int s = g_csrsrc[e];
            float2 u = *((const float2*)(g_t + (size_t)s * NC) + lane);
            a.x += u.x; a.y += u.y;
        }
        float2 bb = *((const float2*)bias + lane);
        float2 o;
        o.x = fmaxf(fmaf(d, a.x, bb.x), 0.f);
        o.y = fmaxf(fmaf(d, a.y, bb.y), 0.f);
        *((float2*)(g_h + (size_t)gw * NC) + lane) = o;
    }
}

// ---------------- global mean pool (h is [N,64]) ----------------
__global__ void k_pool(const void* __restrict__ batch) {
    int gw = (blockIdx.x * blockDim.x + threadIdx.x) >> 5;
    int lane = threadIdx.x & 31;
    if (gw >= N_NODES) return;
    int g = load_idx(batch, gw);
    float2 v = *((const float2*)(g_h + (size_t)gw * 64) + lane);
    atomicAdd(&g_pool[g * 64 + lane * 2], v.x);
    atomicAdd(&g_pool[g * 64 + lane * 2 + 1], v.y);
    if (lane == 0) atomicAdd(&g_cnt[g], 1.f);
}

// ---------------- FC head (single block) ----------------
__global__ void k_fc(const float* __restrict__ Wf1, const float* __restrict__ bf1,
                     const float* __restrict__ Wf2, const float* __restrict__ bf2,
                     float* __restrict__ out) {
    __shared__ float p[64 * 64];
    __shared__ float a1[64 * 32];
    int tid = threadIdx.x;
    for (int i = tid; i < 64 * 64; i += 256) {
        int g = i >> 6;
        p[i] = g_pool[i] / fmaxf(g_cnt[g], 1.f);
    }
    __syncthreads();
    for (int i = tid; i < 64 * 32; i += 256) {
        int g = i >> 5, c = i & 31;
        float s = bf1[c];
        #pragma unroll 8
        for (int k = 0; k < 64; k++) s = fmaf(p[g * 64 + k], Wf1[k * 32 + c], s);
        a1[i] = fmaxf(s, 0.f);
    }
    __syncthreads();
    for (int i = tid; i < 64 * 10; i += 256) {
        int g = i / 10, c = i % 10;
        float s = bf2[c];
        #pragma unroll
        for (int k = 0; k < 32; k++) s = fmaf(a1[g * 32 + k], Wf2[k * 10 + c], s);
        out[i] = s;
    }
}

// ---------------- launch ----------------
extern "C" void kernel_launch(void* const* d_in, const int* in_sizes, int n_in,
                              void* d_out, int out_size) {
    const float* x     = (const float*)d_in[0];
    const void*  ei    = d_in[1];
    const void*  batch = d_in[2];
    const float* W1  = (const float*)d_in[3];
    const float* b1  = (const float*)d_in[4];
    const float* W2  = (const float*)d_in[5];
    const float* b2  = (const float*)d_in[6];
    const float* W3  = (const float*)d_in[7];
    const float* b3  = (const float*)d_in[8];
    const float* Wf1 = (const float*)d_in[9];
    const float* bf1 = (const float*)d_in[10];
    const float* Wf2 = (const float*)d_in[11];
    const float* bf2 = (const float*)d_in[12];
    float* out = (float*)d_out;

    const int EB = (N_EDGES + 255) / 256;
    const int GB = (N_NODES + 63) / 64;               // gemm blocks (64 rows each)
    const int AB = (N_NODES * 32 + 255) / 256;        // warp-per-node blocks

    k_detect<<<1, 32>>>((const int*)ei);
    k_zero<<<64, 256>>>();
    k_hist<<<EB, 256>>>(ei);
    k_scan<<<1, 1024>>>();
    k_fill<<<EB, 256>>>(ei);

    k_gemm<128, false><<<GB, 256>>>(x, W1);
    k_agg<128><<<AB, 256>>>(b1);
    k_gemm<128, true><<<GB, 256>>>(nullptr, W2);
    k_agg<128><<<AB, 256>>>(b2);
    k_gemm<64, true><<<GB, 256>>>(nullptr, W3);
    k_agg<64><<<AB, 256>>>(b3);

    k_pool<<<AB, 256>>>(batch);
    k_fc<<<1, 256>>>(Wf1, bf1, Wf2, bf2, out);
}

// round 9
// speedup vs baseline: 1.2189x; 1.2189x over previous
#include <cuda_runtime.h>
#include <cuda_bf16.h>

#define N_NODES 50000
#define N_EDGES 600000
#define N_GRAPHS 64
#define SCAN_BLOCKS ((N_NODES + 1023) / 1024)   // 49

// ---------------- scratch (no allocations allowed) ----------------
__device__ float g_t[(size_t)N_NODES * 128];   // GEMM output u = dinv * (h@W)
__device__ float g_h[(size_t)N_NODES * 128];   // layer activations
__device__ float g_dinv[N_NODES];
__device__ int   g_indeg[N_NODES];
__device__ int   g_rowptr[N_NODES + 1];
__device__ int   g_cursor[N_NODES];
__device__ int   g_csrsrc[N_EDGES];
__device__ int   g_bsum[SCAN_BLOCKS];
__device__ float g_pool[N_GRAPHS * 64];
__device__ float g_cnt[N_GRAPHS];
__device__ int   g_is64;                       // 1 if edge_index/batch are int64

// index loader robust to int32 vs int64 storage
__device__ __forceinline__ int load_idx(const void* __restrict__ p, size_t i) {
    if (g_is64) return (int)((const long long*)p)[i];
    return ((const int*)p)[i];
}

// ---------------- dtype detection ----------------
__global__ void k_detect(const int* __restrict__ ei_words) {
    int lane = threadIdx.x;
    int nz = 0;
    for (int i = lane; i < 256; i += 32)
        nz |= ei_words[2 * i + 1];              // candidate int64 high words
    for (int off = 16; off; off >>= 1)
        nz |= __shfl_xor_sync(0xffffffffu, nz, off);
    if (lane == 0) g_is64 = (nz == 0) ? 1 : 0;
}

// ---------------- prep kernels ----------------
__global__ void k_zero() {
    int i = blockIdx.x * blockDim.x + threadIdx.x;
    int stride = gridDim.x * blockDim.x;
    for (int j = i; j < N_NODES; j += stride) { g_indeg[j] = 0; g_cursor[j] = 0; }
    if (i < N_GRAPHS * 64) g_pool[i] = 0.f;
    if (i < N_GRAPHS) g_cnt[i] = 0.f;
}

__global__ void k_hist(const void* __restrict__ ei) {
    int e = blockIdx.x * blockDim.x + threadIdx.x;
    if (e < N_EDGES) {
        int c = load_idx(ei, (size_t)N_EDGES + e);
        atomicAdd(&g_indeg[c], 1);
    }
}

// ---------------- hierarchical scan: indeg -> rowptr, plus dinv ----------------
__global__ void k_scan1() {
    int tid = threadIdx.x;
    int i = blockIdx.x * 1024 + tid;
    int lane = tid & 31, wid = tid >> 5;
    int v = (i < N_NODES) ? g_indeg[i] : 0;
    if (i < N_NODES) g_dinv[i] = rsqrtf((float)(v + 1));

    // warp inclusive scan
    int s = v;
    #pragma unroll
    for (int off = 1; off < 32; off <<= 1) {
        int t = __shfl_up_sync(0xffffffffu, s, off);
        if (lane >= off) s += t;
    }
    __shared__ int wsum[32];
    if (lane == 31) wsum[wid] = s;
    __syncthreads();
    if (wid == 0) {
        int w = wsum[lane];
        #pragma unroll
        for (int off = 1; off < 32; off <<= 1) {
            int t = __shfl_up_sync(0xffffffffu, w, off);
            if (lane >= off) w += t;
        }
        wsum[lane] = w;
    }
    __syncthreads();
    int incl = s + (wid ? wsum[wid - 1] : 0);
    if (i < N_NODES) g_rowptr[i + 1] = incl;     // block-local inclusive
    if (tid == 1023) g_bsum[blockIdx.x] = incl;  // block total
}

__global__ void k_scan2() {
    if (threadIdx.x == 0) {
        int acc = 0;
        #pragma unroll 7
        for (int b = 0; b < SCAN_BLOCKS; b++) {
            int t = g_bsum[b]; g_bsum[b] = acc; acc += t;
        }
        g_rowptr[0] = 0;
    }
}

__global__ void k_scan3() {
    int i = blockIdx.x * 1024 + threadIdx.x;
    if (i < N_NODES && blockIdx.x > 0) g_rowptr[i + 1] += g_bsum[blockIdx.x];
}

__global__ void k_fill(const void* __restrict__ ei) {
    int e = blockIdx.x * blockDim.x + threadIdx.x;
    if (e < N_EDGES) {
        int c = load_idx(ei, (size_t)N_EDGES + e);
        int pos = g_rowptr[c] + atomicAdd(&g_cursor[c], 1);
        g_csrsrc[pos] = load_idx(ei, e);
    }
}

// ---------------- GEMM: g_t = dinv * (A @ W),  A:[N,128], W:[128,NC] ----------------
template <int NC, bool FROM_GH>
__global__ __launch_bounds__(256) void k_gemm(const float* __restrict__ Ax,
                                              const float* __restrict__ W) {
    const float* __restrict__ A = FROM_GH ? (const float*)g_h : Ax;
    __shared__ float As[64 * 128];   // 32 KB
    __shared__ float Ws[32 * NC];    // 16 KB (NC=128) / 8 KB (NC=64)
    int tid = threadIdx.x;
    int base = blockIdx.x * 64;

    #pragma unroll
    for (int i = tid; i < 64 * 128 / 4; i += 256) {
        int r = i >> 5, c4 = i & 31;
        float4 v;
        if (base + r < N_NODES) v = *(const float4*)(A + (size_t)(base + r) * 128 + c4 * 4);
        else v = make_float4(0.f, 0.f, 0.f, 0.f);
        ((float4*)As)[i] = v;
    }

    int tx = tid & 31, ty = tid >> 5;
    constexpr int CJ = NC / 32;
    float acc[8][CJ];
    #pragma unroll
    for (int i = 0; i < 8; i++)
        #pragma unroll
        for (int j = 0; j < CJ; j++) acc[i][j] = 0.f;

    #pragma unroll
    for (int kc = 0; kc < 4; kc++) {
        __syncthreads();
        #pragma unroll
        for (int i = tid; i < 32 * NC / 4; i += 256)
            ((float4*)Ws)[i] = ((const float4*)(W + kc * 32 * NC))[i];
        __syncthreads();

        #pragma unroll 4
        for (int k = 0; k < 32; k++) {
            float b[CJ];
            #pragma unroll
            for (int j = 0; j < CJ; j++) b[j] = Ws[k * NC + tx + 32 * j];
            #pragma unroll
            for (int i = 0; i < 8; i++) {
                float a = As[(ty * 8 + i) * 128 + kc * 32 + k];
                #pragma unroll
                for (int j = 0; j < CJ; j++) acc[i][j] = fmaf(a, b[j], acc[i][j]);
            }
        }
    }

    #pragma unroll
    for (int i = 0; i < 8; i++) {
        int r = base + ty * 8 + i;
        if (r < N_NODES) {
            float d = g_dinv[r];
            #pragma unroll
            for (int j = 0; j < CJ; j++)
                g_t[(size_t)r * NC + tx + 32 * j] = d * acc[i][j];
        }
    }
}

// ---------------- aggregation: g_h[v] = relu(dinv[v]*(u[v] + sum_in u[src]) + b) ----------------
template <int NC>
__global__ void k_agg(const float* __restrict__ bias) {
    int gw = (blockIdx.x * blockDim.x + threadIdx.x) >> 5;
    int lane = threadIdx.x & 31;
    if (gw >= N_NODES) return;
    int beg = g_rowptr[gw], end = g_rowptr[gw + 1];
    float d = g_dinv[gw];

    if constexpr (NC == 128) {
        float4 a = *((const float4*)(g_t + (size_t)gw * NC) + lane);
        for (int e = beg; e < end; e++) {
            int s = g_csrsrc[e];
            float4 u = *((const float4*)(g_t + (size_t)s * NC) + lane);
            a.x += u.x; a.y += u.y; a.z += u.z; a.w += u.w;
        }
        float4 bb = *((const float4*)bias + lane);
        float4 o;
        o.x = fmaxf(fmaf(d, a.x, bb.x), 0.f);
        o.y = fmaxf(fmaf(d, a.y, bb.y), 0.f);
        o.z = fmaxf(fmaf(d, a.z, bb.z), 0.f);
        o.w = fmaxf(fmaf(d, a.w, bb.w), 0.f);
        *((float4*)(g_h + (size_t)gw * NC) + lane) = o;
    } else {
        float2 a = *((const float2*)(g_t + (size_t)gw * NC) + lane);
        for (int e = beg; e < end; e++) {
            int s = g_csrsrc[e];
            float2 u = *((const float2*)(g_t + (size_t)s * NC) + lane);
            a.x += u.x; a.y += u.y;
        }
        float2 bb = *((const float2*)bias + lane);
        float2 o;
        o.x = fmaxf(fmaf(d, a.x, bb.x), 0.f);
        o.y = fmaxf(fmaf(d, a.y, bb.y), 0.f);
        *((float2*)(g_h + (size_t)gw * NC) + lane) = o;
    }
}

// ---------------- global mean pool (h is [N,64]) ----------------
__global__ void k_pool(const void* __restrict__ batch) {
    int gw = (blockIdx.x * blockDim.x + threadIdx.x) >> 5;
    int lane = threadIdx.x & 31;
    if (gw >= N_NODES) return;
    int g = load_idx(batch, gw);
    float2 v = *((const float2*)(g_h + (size_t)gw * 64) + lane);
    atomicAdd(&g_pool[g * 64 + lane * 2], v.x);
    atomicAdd(&g_pool[g * 64 + lane * 2 + 1], v.y);
    if (lane == 0) atomicAdd(&g_cnt[g], 1.f);
}

// ---------------- FC head (single block) ----------------
__global__ void k_fc(const float* __restrict__ Wf1, const float* __restrict__ bf1,
                     const float* __restrict__ Wf2, const float* __restrict__ bf2,
                     float* __restrict__ out) {
    __shared__ float p[64 * 64];
    __shared__ float a1[64 * 32];
    int tid = threadIdx.x;
    for (int i = tid; i < 64 * 64; i += 256) {
        int g = i >> 6;
        p[i] = g_pool[i] / fmaxf(g_cnt[g], 1.f);
    }
    __syncthreads();
    for (int i = tid; i < 64 * 32; i += 256) {
        int g = i >> 5, c = i & 31;
        float s = bf1[c];
        #pragma unroll 8
        for (int k = 0; k < 64; k++) s = fmaf(p[g * 64 + k], Wf1[k * 32 + c], s);
        a1[i] = fmaxf(s, 0.f);
    }
    __syncthreads();
    for (int i = tid; i < 64 * 10; i += 256) {
        int g = i / 10, c = i % 10;
        float s = bf2[c];
        #pragma unroll
        for (int k = 0; k < 32; k++) s = fmaf(a1[g * 32 + k], Wf2[k * 10 + c], s);
        out[i] = s;
    }
}

// ---------------- launch ----------------
extern "C" void kernel_launch(void* const* d_in, const int* in_sizes, int n_in,
                              void* d_out, int out_size) {
    const float* x     = (const float*)d_in[0];
    const void*  ei    = d_in[1];
    const void*  batch = d_in[2];
    const float* W1  = (const float*)d_in[3];
    const float* b1  = (const float*)d_in[4];
    const float* W2  = (const float*)d_in[5];
    const float* b2  = (const float*)d_in[6];
    const float* W3  = (const float*)d_in[7];
    const float* b3  = (const float*)d_in[8];
    const float* Wf1 = (const float*)d_in[9];
    const float* bf1 = (const float*)d_in[10];
    const float* Wf2 = (const float*)d_in[11];
    const float* bf2 = (const float*)d_in[12];
    float* out = (float*)d_out;

    const int EB = (N_EDGES + 255) / 256;
    const int GB = (N_NODES + 63) / 64;
    const int AB = (N_NODES * 32 + 255) / 256;

    k_detect<<<1, 32>>>((const int*)ei);
    k_zero<<<64, 256>>>();
    k_hist<<<EB, 256>>>(ei);
    k_scan1<<<SCAN_BLOCKS, 1024>>>();
    k_scan2<<<1, 32>>>();
    k_scan3<<<SCAN_BLOCKS, 1024>>>();
    k_fill<<<EB, 256>>>(ei);

    k_gemm<128, false><<<GB, 256>>>(x, W1);
    k_agg<128><<<AB, 256>>>(b1);
    k_gemm<128, true><<<GB, 256>>>(nullptr, W2);
    k_agg<128><<<AB, 256>>>(b2);
    k_gemm<64, true><<<GB, 256>>>(nullptr, W3);
    k_agg<64><<<AB, 256>>>(b3);

    k_pool<<<AB, 256>>>(batch);
    k_fc<<<1, 256>>>(Wf1, bf1, Wf2, bf2, out);
}

// round 11
// speedup vs baseline: 1.3540x; 1.1108x over previous
#include <cuda_runtime.h>
#include <cuda_bf16.h>
#include <cstdint>

#define N_NODES 50000
#define N_EDGES 600000
#define N_GRAPHS 64
#define SCAN_BLOCKS ((N_NODES + 1023) / 1024)   // 49

// ---------------- scratch (no allocations allowed) ----------------
__device__ float g_t[(size_t)N_NODES * 128];   // GEMM output u = dinv * (h@W)
__device__ float g_h[(size_t)N_NODES * 128];   // layer activations
__device__ float g_dinv[N_NODES];
__device__ int   g_indeg[N_NODES];
__device__ int   g_rowptr[N_NODES + 1];
__device__ int   g_cursor[N_NODES];
__device__ int   g_csrsrc[N_EDGES];
__device__ int   g_bsum[SCAN_BLOCKS];
__device__ float g_pool[N_GRAPHS * 64];
__device__ float g_cnt[N_GRAPHS];
__device__ int   g_is64;

// index loader robust to int32 vs int64 storage
__device__ __forceinline__ int load_idx(const void* __restrict__ p, size_t i) {
    if (g_is64) return (int)((const long long*)p)[i];
    return ((const int*)p)[i];
}

// ---------------- dtype detection ----------------
__global__ void k_detect(const int* __restrict__ ei_words) {
    int lane = threadIdx.x;
    int nz = 0;
    for (int i = lane; i < 256; i += 32)
        nz |= ei_words[2 * i + 1];
    for (int off = 16; off; off >>= 1)
        nz |= __shfl_xor_sync(0xffffffffu, nz, off);
    if (lane == 0) g_is64 = (nz == 0) ? 1 : 0;
}

// ---------------- prep kernels ----------------
__global__ void k_zero() {
    int i = blockIdx.x * blockDim.x + threadIdx.x;
    int stride = gridDim.x * blockDim.x;
    for (int j = i; j < N_NODES; j += stride) { g_indeg[j] = 0; g_cursor[j] = 0; }
    if (i < N_GRAPHS * 64) g_pool[i] = 0.f;
    if (i < N_GRAPHS) g_cnt[i] = 0.f;
}

__global__ void k_hist(const void* __restrict__ ei) {
    int e = blockIdx.x * blockDim.x + threadIdx.x;
    if (e < N_EDGES) atomicAdd(&g_indeg[load_idx(ei, (size_t)N_EDGES + e)], 1);
}

__global__ void k_scan1() {
    int tid = threadIdx.x;
    int i = blockIdx.x * 1024 + tid;
    int lane = tid & 31, wid = tid >> 5;
    int v = (i < N_NODES) ? g_indeg[i] : 0;
    if (i < N_NODES) g_dinv[i] = rsqrtf((float)(v + 1));
    int s = v;
    #pragma unroll
    for (int off = 1; off < 32; off <<= 1) {
        int t = __shfl_up_sync(0xffffffffu, s, off);
        if (lane >= off) s += t;
    }
    __shared__ int wsum[32];
    if (lane == 31) wsum[wid] = s;
    __syncthreads();
    if (wid == 0) {
        int w = wsum[lane];
        #pragma unroll
        for (int off = 1; off < 32; off <<= 1) {
            int t = __shfl_up_sync(0xffffffffu, w, off);
            if (lane >= off) w += t;
        }
        wsum[lane] = w;
    }
    __syncthreads();
    int incl = s + (wid ? wsum[wid - 1] : 0);
    if (i < N_NODES) g_rowptr[i + 1] = incl;
    if (tid == 1023) g_bsum[blockIdx.x] = incl;
}

__global__ void k_scan2() {
    if (threadIdx.x == 0) {
        int acc = 0;
        for (int b = 0; b < SCAN_BLOCKS; b++) { int t = g_bsum[b]; g_bsum[b] = acc; acc += t; }
        g_rowptr[0] = 0;
    }
}

__global__ void k_scan3() {
    int i = blockIdx.x * 1024 + threadIdx.x;
    if (i < N_NODES && blockIdx.x > 0) g_rowptr[i + 1] += g_bsum[blockIdx.x];
}

__global__ void k_fill(const void* __restrict__ ei) {
    int e = blockIdx.x * blockDim.x + threadIdx.x;
    if (e < N_EDGES) {
        int c = load_idx(ei, (size_t)N_EDGES + e);
        int pos = g_rowptr[c] + atomicAdd(&g_cursor[c], 1);
        g_csrsrc[pos] = load_idx(ei, e);
    }
}

// ---------------- HMMA GEMM: g_t = dinv * (A @ W) ----------------
// A:[N,128] fp32, W:[128,NC] fp32. bf16 hi/lo split, 3-term mma.sync
// (Ah*Bh + Ah*Bl + Al*Bh), fp32 register accumulators.
// Smem: A as [row][k] (stride 136 bf16), B = W^T as [n][k] (stride 136 bf16).
#define APAD 136

__device__ __forceinline__ void mma16816(float* d, const uint32_t* a,
                                         uint32_t b0, uint32_t b1) {
    asm volatile(
        "mma.sync.aligned.m16n8k16.row.col.f32.bf16.bf16.f32 "
        "{%0,%1,%2,%3}, {%4,%5,%6,%7}, {%8,%9}, {%0,%1,%2,%3};"
        : "+f"(d[0]), "+f"(d[1]), "+f"(d[2]), "+f"(d[3])
        : "r"(a[0]), "r"(a[1]), "r"(a[2]), "r"(a[3]), "r"(b0), "r"(b1));
}

template <int NC, bool FROM_GH>
__global__ __launch_bounds__(256) void k_mma(const float* __restrict__ Ax,
                                             const float* __restrict__ W) {
    const float* __restrict__ A = FROM_GH ? (const float*)g_h : Ax;
    extern __shared__ __nv_bfloat16 sm[];
    __nv_bfloat16* AH = sm;                    // [128][APAD]
    __nv_bfloat16* AL = AH + 128 * APAD;
    __nv_bfloat16* BH = AL + 128 * APAD;       // [NC][APAD]
    __nv_bfloat16* BL = BH + NC * APAD;

    const int tid = threadIdx.x;
    const int wid = tid >> 5, lane = tid & 31;
    const int base = blockIdx.x * 128;

    // ---- stage A: 128 rows x 128 k, hi/lo split, paired stores ----
    for (int idx = tid; idx < 128 * 64; idx += 256) {
        int row = idx >> 6, kp = (idx & 63) * 2;
        float2 v = make_float2(0.f, 0.f);
        if (base + row < N_NODES)
            v = *(const float2*)(A + (size_t)(base + row) * 128 + kp);
        __nv_bfloat16 h0 = __float2bfloat16(v.x), h1 = __float2bfloat16(v.y);
        __nv_bfloat16 l0 = __float2bfloat16(v.x - __bfloat162float(h0));
        __nv_bfloat16 l1 = __float2bfloat16(v.y - __bfloat162float(h1));
        *(__nv_bfloat162*)(AH + row * APAD + kp) = __nv_bfloat162(h0, h1);
        *(__nv_bfloat162*)(AL + row * APAD + kp) = __nv_bfloat162(l0, l1);
    }
    // ---- stage B = W^T: W[k][n] -> B[n][k], hi/lo split ----
    for (int idx = tid; idx < 128 * NC; idx += 256) {
        int k = idx / NC, n = idx % NC;        // coalesced W read
        float w = W[idx];
        __nv_bfloat16 h = __float2bfloat16(w);
        BH[n * APAD + k] = h;
        BL[n * APAD + k] = __float2bfloat16(w - __bfloat162float(h));
    }
    __syncthreads();

    // ---- mma mainloop: warp -> rows [16*wid, 16*wid+16), all NC cols ----
    constexpr int NT = NC / 8;
    float acc[NT][4];
    #pragma unroll
    for (int t = 0; t < NT; t++)
        #pragma unroll
        for (int j = 0; j < 4; j++) acc[t][j] = 0.f;

    const int g = lane >> 2;                   // 0..7
    const int kq = (lane & 3) * 2;             // 0,2,4,6
    const int r0 = wid * 16 + g, r1 = r0 + 8;

    #pragma unroll
    for (int ks = 0; ks < 8; ks++) {
        int kb = ks * 16 + kq;
        uint32_t ah[4], al[4];
        ah[0] = *(const uint32_t*)(AH + r0 * APAD + kb);
        ah[1] = *(const uint32_t*)(AH + r1 * APAD + kb);
        ah[2] = *(const uint32_t*)(AH + r0 * APAD + kb + 8);
        ah[3] = *(const uint32_t*)(AH + r1 * APAD + kb + 8);
        al[0] = *(const uint32_t*)(AL + r0 * APAD + kb);
        al[1] = *(const uint32_t*)(AL + r1 * APAD + kb);
        al[2] = *(const uint32_t*)(AL + r0 * APAD + kb + 8);
        al[3] = *(const uint32_t*)(AL + r1 * APAD + kb + 8);
        #pragma unroll
        for (int nt = 0; nt < NT; nt++) {
            int n = nt * 8 + g;
            uint32_t bh0 = *(const uint32_t*)(BH + n * APAD + kb);
            uint32_t bh1 = *(const uint32_t*)(BH + n * APAD + kb + 8);
            uint32_t bl0 = *(const uint32_t*)(BL + n * APAD + kb);
            uint32_t bl1 = *(const uint32_t*)(BL + n * APAD + kb + 8);
            mma16816(acc[nt], ah, bh0, bh1);
            mma16816(acc[nt], ah, bl0, bl1);
            mma16816(acc[nt], al, bh0, bh1);
        }
    }

    // ---- epilogue: scale by dinv, write g_t ----
    int row0 = base + r0, row1 = base + r1;
    float d0 = (row0 < N_NODES) ? g_dinv[row0] : 0.f;
    float d1 = (row1 < N_NODES) ? g_dinv[row1] : 0.f;
    #pragma unroll
    for (int nt = 0; nt < NT; nt++) {
        int col = nt * 8 + kq;
        if (row0 < N_NODES)
            *(float2*)(g_t + (size_t)row0 * NC + col) = make_float2(d0 * acc[nt][0], d0 * acc[nt][1]);
        if (row1 < N_NODES)
            *(float2*)(g_t + (size_t)row1 * NC + col) = make_float2(d1 * acc[nt][2], d1 * acc[nt][3]);
    }
}

// ---------------- aggregation: g_h[v] = relu(dinv[v]*(u[v] + sum_in u[src]) + b) ----------------
template <int NC>
__global__ void k_agg(const float* __restrict__ bias) {
    int gw = (blockIdx.x * blockDim.x + threadIdx.x) >> 5;
    int lane = threadIdx.x & 31;
    if (gw >= N_NODES) return;
    int beg = g_rowptr[gw], end = g_rowptr[gw + 1];
    float d = g_dinv[gw];

    if constexpr (NC == 128) {
        float4 a = *((const float4*)(g_t + (size_t)gw * NC) + lane);
        for (int e = beg; e < end; e++) {
            int s = g_csrsrc[e];
            float4 u = *((const float4*)(g_t + (size_t)s * NC) + lane);
            a.x += u.x; a.y += u.y; a.z += u.z; a.w += u.w;
        }
        float4 bb = *((const float4*)bias + lane);
        float4 o;
        o.x = fmaxf(fmaf(d, a.x, bb.x), 0.f);
        o.y = fmaxf(fmaf(d, a.y, bb.y), 0.f);
        o.z = fmaxf(fmaf(d, a.z, bb.z), 0.f);
        o.w = fmaxf(fmaf(d, a.w, bb.w), 0.f);
        *((float4*)(g_h + (size_t)gw * NC) + lane) = o;
    } else {
        float2 a = *((const float2*)(g_t + (size_t)gw * NC) + lane);
        for (int e = beg; e < end; e++) {
            int s = g_csrsrc[e];
            float2 u = *((const float2*)(g_t + (size_t)s * NC) + lane);
            a.x += u.x; a.y += u.y;
        }
        float2 bb = *((const float2*)bias + lane);
        float2 o;
        o.x = fmaxf(fmaf(d, a.x, bb.x), 0.f);
        o.y = fmaxf(fmaf(d, a.y, bb.y), 0.f);
        *((float2*)(g_h + (size_t)gw * NC) + lane) = o;
    }
}

// ---------------- global mean pool (h is [N,64]) ----------------
__global__ void k_pool(const void* __restrict__ batch) {
    int gw = (blockIdx.x * blockDim.x + threadIdx.x) >> 5;
    int lane = threadIdx.x & 31;
    if (gw >= N_NODES) return;
    int g = load_idx(batch, gw);
    float2 v = *((const float2*)(g_h + (size_t)gw * 64) + lane);
    atomicAdd(&g_pool[g * 64 + lane * 2], v.x);
    atomicAdd(&g_pool[g * 64 + lane * 2 + 1], v.y);
    if (lane == 0) atomicAdd(&g_cnt[g], 1.f);
}

// ---------------- FC head (single block) ----------------
__global__ void k_fc(const float* __restrict__ Wf1, const float* __restrict__ bf1,
                     const float* __restrict__ Wf2, const float* __restrict__ bf2,
                     float* __restrict__ out) {
    __shared__ float p[64 * 64];
    __shared__ float a1[64 * 32];
    int tid = threadIdx.x;
    for (int i = tid; i < 64 * 64; i += 256) {
        int g = i >> 6;
        p[i] = g_pool[i] / fmaxf(g_cnt[g], 1.f);
    }
    __syncthreads();
    for (int i = tid; i < 64 * 32; i += 256) {
        int g = i >> 5, c = i & 31;
        float s = bf1[c];
        #pragma unroll 8
        for (int k = 0; k < 64; k++) s = fmaf(p[g * 64 + k], Wf1[k * 32 + c], s);
        a1[i] = fmaxf(s, 0.f);
    }
    __syncthreads();
    for (int i = tid; i < 64 * 10; i += 256) {
        int g = i / 10, c = i % 10;
        float s = bf2[c];
        #pragma unroll
        for (int k = 0; k < 32; k++) s = fmaf(a1[g * 32 + k], Wf2[k * 10 + c], s);
        out[i] = s;
    }
}

// ---------------- launch ----------------
extern "C" void kernel_launch(void* const* d_in, const int* in_sizes, int n_in,
                              void* d_out, int out_size) {
    const float* x     = (const float*)d_in[0];
    const void*  ei    = d_in[1];
    const void*  batch = d_in[2];
    const float* W1  = (const float*)d_in[3];
    const float* b1  = (const float*)d_in[4];
    const float* W2  = (const float*)d_in[5];
    const float* b2  = (const float*)d_in[6];
    const float* W3  = (const float*)d_in[7];
    const float* b3  = (const float*)d_in[8];
    const float* Wf1 = (const float*)d_in[9];
    const float* bf1 = (const float*)d_in[10];
    const float* Wf2 = (const float*)d_in[11];
    const float* bf2 = (const float*)d_in[12];
    float* out = (float*)d_out;

    const int EB  = (N_EDGES + 255) / 256;
    const int AB  = (N_NODES * 32 + 255) / 256;
    const int MB  = (N_NODES + 127) / 128;     // 391

    const int SM128 = (2 * 128 * APAD + 2 * 128 * APAD) * 2;  // 139264
    const int SM64  = (2 * 128 * APAD + 2 * 64 * APAD) * 2;   // 104448
    cudaFuncSetAttribute(k_mma<128, false>, cudaFuncAttributeMaxDynamicSharedMemorySize, SM128);
    cudaFuncSetAttribute(k_mma<128, true>,  cudaFuncAttributeMaxDynamicSharedMemorySize, SM128);
    cudaFuncSetAttribute(k_mma<64, true>,   cudaFuncAttributeMaxDynamicSharedMemorySize, SM64);

    k_detect<<<1, 32>>>((const int*)ei);
    k_zero<<<64, 256>>>();
    k_hist<<<EB, 256>>>(ei);
    k_scan1<<<SCAN_BLOCKS, 1024>>>();
    k_scan2<<<1, 32>>>();
    k_scan3<<<SCAN_BLOCKS, 1024>>>();
    k_fill<<<EB, 256>>>(ei);

    k_mma<128, false><<<MB, 256, SM128>>>(x, W1);
    k_agg<128><<<AB, 256>>>(b1);
    k_mma<128, true><<<MB, 256, SM128>>>(nullptr, W2);
    k_agg<128><<<AB, 256>>>(b2);
    k_mma<64, true><<<MB, 256, SM64>>>(nullptr, W3);
    k_agg<64><<<AB, 256>>>(b3);

    k_pool<<<AB, 256>>>(batch);
    k_fc<<<1, 256>>>(Wf1, bf1, Wf2, bf2, out);
}

// round 12
// speedup vs baseline: 1.5287x; 1.1290x over previous
#include <cuda_runtime.h>
#include <cuda_bf16.h>
#include <cstdint>

#define N_NODES 50000
#define N_EDGES 600000
#define N_GRAPHS 64
#define SCAN_BLOCKS ((N_NODES + 1023) / 1024)   // 49

// ---------------- scratch (no allocations allowed) ----------------
__device__ float g_t[(size_t)N_NODES * 128];   // GEMM output u = dinv * (h@W)
__device__ float g_h[(size_t)N_NODES * 128];   // layer activations
__device__ float g_dinv[N_NODES];
__device__ int   g_indeg[N_NODES];
__device__ int   g_rowptr[N_NODES + 1];
__device__ int   g_cursor[N_NODES];
__device__ int   g_csrsrc[N_EDGES];
__device__ int   g_bsum[SCAN_BLOCKS];
__device__ float g_pool[N_GRAPHS * 64];
__device__ float g_cnt[N_GRAPHS];
__device__ int   g_is64;

// index loader robust to int32 vs int64 storage
__device__ __forceinline__ int load_idx(const void* __restrict__ p, size_t i) {
    if (g_is64) return (int)((const long long*)p)[i];
    return ((const int*)p)[i];
}

// ---------------- zero + dtype detect (fused) ----------------
__global__ void k_zero(const int* __restrict__ ei_words) {
    int i = blockIdx.x * blockDim.x + threadIdx.x;
    int stride = gridDim.x * blockDim.x;
    if (blockIdx.x == 0 && threadIdx.x < 32) {
        int lane = threadIdx.x;
        int nz = 0;
        for (int j = lane; j < 256; j += 32)
            nz |= ei_words[2 * j + 1];          // candidate int64 high words
        for (int off = 16; off; off >>= 1)
            nz |= __shfl_xor_sync(0xffffffffu, nz, off);
        if (lane == 0) g_is64 = (nz == 0) ? 1 : 0;
    }
    for (int j = i; j < N_NODES; j += stride) { g_indeg[j] = 0; g_cursor[j] = 0; }
    if (i < N_GRAPHS * 64) g_pool[i] = 0.f;
    if (i < N_GRAPHS) g_cnt[i] = 0.f;
}

__global__ void k_hist(const void* __restrict__ ei) {
    int e = blockIdx.x * blockDim.x + threadIdx.x;
    if (e < N_EDGES) atomicAdd(&g_indeg[load_idx(ei, (size_t)N_EDGES + e)], 1);
}

__global__ void k_scan1() {
    int tid = threadIdx.x;
    int i = blockIdx.x * 1024 + tid;
    int lane = tid & 31, wid = tid >> 5;
    int v = (i < N_NODES) ? g_indeg[i] : 0;
    if (i < N_NODES) g_dinv[i] = rsqrtf((float)(v + 1));
    int s = v;
    #pragma unroll
    for (int off = 1; off < 32; off <<= 1) {
        int t = __shfl_up_sync(0xffffffffu, s, off);
        if (lane >= off) s += t;
    }
    __shared__ int wsum[32];
    if (lane == 31) wsum[wid] = s;
    __syncthreads();
    if (wid == 0) {
        int w = wsum[lane];
        #pragma unroll
        for (int off = 1; off < 32; off <<= 1) {
            int t = __shfl_up_sync(0xffffffffu, w, off);
            if (lane >= off) w += t;
        }
        wsum[lane] = w;
    }
    __syncthreads();
    int incl = s + (wid ? wsum[wid - 1] : 0);
    if (i < N_NODES) g_rowptr[i + 1] = incl;
    if (tid == 1023) g_bsum[blockIdx.x] = incl;
}

__global__ void k_scan2() {
    if (threadIdx.x == 0) {
        int acc = 0;
        for (int b = 0; b < SCAN_BLOCKS; b++) { int t = g_bsum[b]; g_bsum[b] = acc; acc += t; }
        g_rowptr[0] = 0;
    }
}

__global__ void k_scan3() {
    int i = blockIdx.x * 1024 + threadIdx.x;
    if (i < N_NODES && blockIdx.x > 0) g_rowptr[i + 1] += g_bsum[blockIdx.x];
}

__global__ void k_fill(const void* __restrict__ ei) {
    int e = blockIdx.x * blockDim.x + threadIdx.x;
    if (e < N_EDGES) {
        int c = load_idx(ei, (size_t)N_EDGES + e);
        int pos = g_rowptr[c] + atomicAdd(&g_cursor[c], 1);
        g_csrsrc[pos] = load_idx(ei, e);
    }
}

// ---------------- HMMA GEMM: g_t = dinv * (A @ W) ----------------
// bf16 hi/lo split, 3-term mma.sync (Ah*Bh + Ah*Bl + Al*Bh), fp32 acc.
// B = W^T staged in smem ([n][k], stride APAD bf16). A fragments loaded
// directly from gmem per warp (no A smem) -> 2 CTAs/SM.
#define APAD 136

__device__ __forceinline__ void mma16816(float* d, const uint32_t* a,
                                         uint32_t b0, uint32_t b1) {
    asm volatile(
        "mma.sync.aligned.m16n8k16.row.col.f32.bf16.bf16.f32 "
        "{%0,%1,%2,%3}, {%4,%5,%6,%7}, {%8,%9}, {%0,%1,%2,%3};"
        : "+f"(d[0]), "+f"(d[1]), "+f"(d[2]), "+f"(d[3])
        : "r"(a[0]), "r"(a[1]), "r"(a[2]), "r"(a[3]), "r"(b0), "r"(b1));
}

__device__ __forceinline__ void split2(float2 v, uint32_t& hi, uint32_t& lo) {
    __nv_bfloat16 h0 = __float2bfloat16(v.x), h1 = __float2bfloat16(v.y);
    __nv_bfloat16 l0 = __float2bfloat16(v.x - __bfloat162float(h0));
    __nv_bfloat16 l1 = __float2bfloat16(v.y - __bfloat162float(h1));
    __nv_bfloat162 H(h0, h1), L(l0, l1);
    hi = *(uint32_t*)&H;
    lo = *(uint32_t*)&L;
}

template <int NC, bool FROM_GH>
__global__ __launch_bounds__(256, 2) void k_mma(const float* __restrict__ Ax,
                                                const float* __restrict__ W) {
    const float* __restrict__ A = FROM_GH ? (const float*)g_h : Ax;
    extern __shared__ __nv_bfloat16 sm[];
    __nv_bfloat16* BH = sm;                    // [NC][APAD]
    __nv_bfloat16* BL = BH + NC * APAD;

    const int tid = threadIdx.x;
    const int wid = tid >> 5, lane = tid & 31;
    const int base = blockIdx.x * 128;

    // ---- stage B = W^T: W[k][n] -> B[n][k], hi/lo split ----
    for (int idx = tid; idx < 128 * NC; idx += 256) {
        int k = idx / NC, n = idx % NC;        // coalesced W read
        float w = W[idx];
        __nv_bfloat16 h = __float2bfloat16(w);
        BH[n * APAD + k] = h;
        BL[n * APAD + k] = __float2bfloat16(w - __bfloat162float(h));
    }
    __syncthreads();

    constexpr int NT = NC / 8;
    float acc[NT][4];
    #pragma unroll
    for (int t = 0; t < NT; t++)
        #pragma unroll
        for (int j = 0; j < 4; j++) acc[t][j] = 0.f;

    const int g = lane >> 2;                   // 0..7
    const int kq = (lane & 3) * 2;             // 0,2,4,6
    const int r0 = wid * 16 + g, r1 = r0 + 8;
    const int gr0 = base + r0, gr1 = base + r1;
    const bool v0 = gr0 < N_NODES, v1 = gr1 < N_NODES;
    const float* A0 = A + (size_t)gr0 * 128;
    const float* A1 = A + (size_t)gr1 * 128;

    #pragma unroll
    for (int ks = 0; ks < 8; ks++) {
        int kb = ks * 16 + kq;
        float2 z = make_float2(0.f, 0.f);
        float2 va0 = v0 ? *(const float2*)(A0 + kb)     : z;
        float2 va1 = v1 ? *(const float2*)(A1 + kb)     : z;
        float2 vb0 = v0 ? *(const float2*)(A0 + kb + 8) : z;
        float2 vb1 = v1 ? *(const float2*)(A1 + kb + 8) : z;
        uint32_t ah[4], al[4];
        split2(va0, ah[0], al[0]);
        split2(va1, ah[1], al[1]);
        split2(vb0, ah[2], al[2]);
        split2(vb1, ah[3], al[3]);
        #pragma unroll
        for (int nt = 0; nt < NT; nt++) {
            int n = nt * 8 + g;
            uint32_t bh0 = *(const uint32_t*)(BH + n * APAD + kb);
            uint32_t bh1 = *(const uint32_t*)(BH + n * APAD + kb + 8);
            uint32_t bl0 = *(const uint32_t*)(BL + n * APAD + kb);
            uint32_t bl1 = *(const uint32_t*)(BL + n * APAD + kb + 8);
            mma16816(acc[nt], ah, bh0, bh1);
            mma16816(acc[nt], ah, bl0, bl1);
            mma16816(acc[nt], al, bh0, bh1);
        }
    }

    // ---- epilogue: scale by dinv, write g_t ----
    float d0 = v0 ? g_dinv[gr0] : 0.f;
    float d1 = v1 ? g_dinv[gr1] : 0.f;
    #pragma unroll
    for (int nt = 0; nt < NT; nt++) {
        int col = nt * 8 + kq;
        if (v0)
            *(float2*)(g_t + (size_t)gr0 * NC + col) = make_float2(d0 * acc[nt][0], d0 * acc[nt][1]);
        if (v1)
            *(float2*)(g_t + (size_t)gr1 * NC + col) = make_float2(d1 * acc[nt][2], d1 * acc[nt][3]);
    }
}

// ---------------- aggregation (layers 1,2): g_h = relu(dinv*(u[v]+sum u[src])+b) ----------------
__global__ void k_agg128(const float* __restrict__ bias) {
    int gw = (blockIdx.x * blockDim.x + threadIdx.x) >> 5;
    int lane = threadIdx.x & 31;
    if (gw >= N_NODES) return;
    int beg = g_rowptr[gw], end = g_rowptr[gw + 1];
    float d = g_dinv[gw];

    float4 a = *((const float4*)(g_t + (size_t)gw * 128) + lane);
    for (int e = beg; e < end; e++) {
        int s = g_csrsrc[e];
        float4 u = *((const float4*)(g_t + (size_t)s * 128) + lane);
        a.x += u.x; a.y += u.y; a.z += u.z; a.w += u.w;
    }
    float4 bb = *((const float4*)bias + lane);
    float4 o;
    o.x = fmaxf(fmaf(d, a.x, bb.x), 0.f);
    o.y = fmaxf(fmaf(d, a.y, bb.y), 0.f);
    o.z = fmaxf(fmaf(d, a.z, bb.z), 0.f);
    o.w = fmaxf(fmaf(d, a.w, bb.w), 0.f);
    *((float4*)(g_h + (size_t)gw * 128) + lane) = o;
}

// ---------------- layer-3 aggregation fused with mean-pool accumulation ----------------
__global__ void k_agg_pool(const float* __restrict__ bias, const void* __restrict__ batch) {
    int gw = (blockIdx.x * blockDim.x + threadIdx.x) >> 5;
    int lane = threadIdx.x & 31;
    if (gw >= N_NODES) return;
    int beg = g_rowptr[gw], end = g_rowptr[gw + 1];
    float d = g_dinv[gw];

    float2 a = *((const float2*)(g_t + (size_t)gw * 64) + lane);
    for (int e = beg; e < end; e++) {
        int s = g_csrsrc[e];
        float2 u = *((const float2*)(g_t + (size_t)s * 64) + lane);
        a.x += u.x; a.y += u.y;
    }
    float2 bb = *((const float2*)bias + lane);
    float ox = fmaxf(fmaf(d, a.x, bb.x), 0.f);
    float oy = fmaxf(fmaf(d, a.y, bb.y), 0.f);

    int g = load_idx(batch, gw);
    atomicAdd(&g_pool[g * 64 + lane * 2], ox);
    atomicAdd(&g_pool[g * 64 + lane * 2 + 1], oy);
    if (lane == 0) atomicAdd(&g_cnt[g], 1.f);
}

// ---------------- FC head (single block) ----------------
__global__ void k_fc(const float* __restrict__ Wf1, const float* __restrict__ bf1,
                     const float* __restrict__ Wf2, const float* __restrict__ bf2,
                     float* __restrict__ out) {
    __shared__ float p[64 * 64];
    __shared__ float a1[64 * 32];
    int tid = threadIdx.x;
    for (int i = tid; i < 64 * 64; i += 256) {
        int g = i >> 6;
        p[i] = g_pool[i] / fmaxf(g_cnt[g], 1.f);
    }
    __syncthreads();
    for (int i = tid; i < 64 * 32; i += 256) {
        int g = i >> 5, c = i & 31;
        float s = bf1[c];
        #pragma unroll 8
        for (int k = 0; k < 64; k++) s = fmaf(p[g * 64 + k], Wf1[k * 32 + c], s);
        a1[i] = fmaxf(s, 0.f);
    }
    __syncthreads();
    for (int i = tid; i < 64 * 10; i += 256) {
        int g = i / 10, c = i % 10;
        float s = bf2[c];
        #pragma unroll
        for (int k = 0; k < 32; k++) s = fmaf(a1[g * 32 + k], Wf2[k * 10 + c], s);
        out[i] = s;
    }
}

// ---------------- launch ----------------
extern "C" void kernel_launch(void* const* d_in, const int* in_sizes, int n_in,
                              void* d_out, int out_size) {
    const float* x     = (const float*)d_in[0];
    const void*  ei    = d_in[1];
    const void*  batch = d_in[2];
    const float* W1  = (const float*)d_in[3];
    const float* b1  = (const float*)d_in[4];
    const float* W2  = (const float*)d_in[5];
    const float* b2  = (const float*)d_in[6];
    const float* W3  = (const float*)d_in[7];
    const float* b3  = (const float*)d_in[8];
    const float* Wf1 = (const float*)d_in[9];
    const float* bf1 = (const float*)d_in[10];
    const float* Wf2 = (const float*)d_in[11];
    const float* bf2 = (const float*)d_in[12];
    float* out = (float*)d_out;

    const int EB = (N_EDGES + 255) / 256;
    const int AB = (N_NODES * 32 + 255) / 256;
    const int MB = (N_NODES + 127) / 128;      // 391

    const int SM128 = 2 * 128 * APAD * 2;      // 69632 (B hi+lo)
    const int SM64  = 2 * 64 * APAD * 2;       // 34816
    cudaFuncSetAttribute(k_mma<128, false>, cudaFuncAttributeMaxDynamicSharedMemorySize, SM128);
    cudaFuncSetAttribute(k_mma<128, true>,  cudaFuncAttributeMaxDynamicSharedMemorySize, SM128);
    cudaFuncSetAttribute(k_mma<64, true>,   cudaFuncAttributeMaxDynamicSharedMemorySize, SM64);

    k_zero<<<64, 256>>>((const int*)ei);
    k_hist<<<EB, 256>>>(ei);
    k_scan1<<<SCAN_BLOCKS, 1024>>>();
    k_scan2<<<1, 32>>>();
    k_scan3<<<SCAN_BLOCKS, 1024>>>();
    k_fill<<<EB, 256>>>(ei);

    k_mma<128, false><<<MB, 256, SM128>>>(x, W1);
    k_agg128<<<AB, 256>>>(b1);
    k_mma<128, true><<<MB, 256, SM128>>>(nullptr, W2);
    k_agg128<<<AB, 256>>>(b2);
    k_mma<64, true><<<MB, 256, SM64>>>(nullptr, W3);
    k_agg_pool<<<AB, 256>>>(b3, batch);

    k_fc<<<1, 256>>>(Wf1, bf1, Wf2, bf2, out);
}